// round 4
// baseline (speedup 1.0000x reference)
#include <cuda_runtime.h>
#include <cstdint>

#define BATCH    512
#define BITD     64
#define NCLS     100
#define NTRAIN   100000
#define MARGIN_F 128.0f

#define SCAN_BLOCKS 391          // ceil(100000/256)
#define UST_BLOCKS  512

// -------- device accumulators / scratch (no allocations allowed) --------
__device__ double   g_sum_usq;        // sum_b |u_b|^2
__device__ double   g_s2;             // sum |1 - sign(u)|
__device__ double   g_SUsq;           // sum_n |U'_n|^2 (after update)
__device__ double   g_corr;           // hinge correction over mismatch pairs
__device__ double   g_su[BITD];       // column sums of u
__device__ double   g_SU[BITD];       // column sums of U' (after update)
__device__ float    g_usq[BATCH];     // per-row |u_b|^2
__device__ __align__(16) unsigned g_ypk[4 * BATCH]; // packed labels [word][row]

__device__ __forceinline__ float wred(float v) {
#pragma unroll
    for (int o = 16; o; o >>= 1) v += __shfl_xor_sync(0xffffffffu, v, o);
    return v;
}

// --------- rare path: exact pair term 0.5*(max(m-d,0) - d) --------------
// Single definition compiled identically in k_scan and k_fix (same source,
// serial FMA chains -> bit-identical results; cancellation is exact).
__device__ __noinline__ double pair_term(int b, const float* __restrict__ ur,
                                         const float* __restrict__ vr) {
    float dot = 0.f, vsq = 0.f;
#pragma unroll 16
    for (int k = 0; k < BITD; k++) {
        float a = ur[k], c = vr[k];
        dot = fmaf(a, c, dot);
        vsq = fmaf(c, c, vsq);
    }
    float d = g_usq[b] - 2.f * dot + vsq;
    d = fmaxf(d, 0.f);
    return 0.5 * ((double)fmaxf(MARGIN_F - d, 0.f) - (double)d);
}

// Warp-cooperative permuted pack of one row base pointer (row*NCLS floats):
// lane l<25 supplies classes 4l..4l+3. Returns the 4 ballots.
__device__ __forceinline__ uint4 pack_ballots(const float* __restrict__ row,
                                              int lane) {
    float4 v = make_float4(0.f, 0.f, 0.f, 0.f);
    if (lane < 25) v = ((const float4*)row)[lane];
    uint4 r;
    r.x = __ballot_sync(0xffffffffu, v.x != 0.f);
    r.y = __ballot_sync(0xffffffffu, v.y != 0.f);
    r.z = __ballot_sync(0xffffffffu, v.z != 0.f);
    r.w = __ballot_sync(0xffffffffu, v.w != 0.f);
    return r;
}

// ------------------------------------------------- batch stats + y pack
__global__ void k_batch(const float* __restrict__ u,
                        const float* __restrict__ y) {
    __shared__ float ssu[BITD];
    __shared__ float swq[16], sws[16];
    int i    = threadIdx.x;            // 512 threads, 1 block
    int lane = i & 31, warp = i >> 5;

    if (i < BITD) { ssu[i] = 0.f; g_SU[i] = 0.0; }
    if (i == 0) { g_SUsq = 0.0; g_corr = 0.0; }
    __syncthreads();

    const float* ur = u + i * BITD;
    float usq = 0.f, s2 = 0.f;
#pragma unroll
    for (int kk = 0; kk < BITD; kk++) {
        int k = (kk + i) & (BITD - 1);     // staggered: conflict-free in warp
        float v = ur[k];
        usq += v * v;
        s2  += (v > 0.f) ? 0.f : ((v < 0.f) ? 2.f : 1.f);
        atomicAdd(&ssu[k], v);
    }
    g_usq[i] = usq;
    float ru = wred(usq), rs = wred(s2);
    if (lane == 0) { swq[warp] = ru; sws[warp] = rs; }

    // warp-cooperative permuted pack: warp w packs rows 32w..32w+31
    int rbase = warp * 32;
    for (int r = 0; r < 32; r++) {
        uint4 b = pack_ballots(y + (size_t)(rbase + r) * NCLS, lane);
        if (lane == r) {
            g_ypk[rbase + r]             = b.x;
            g_ypk[BATCH + rbase + r]     = b.y;
            g_ypk[2 * BATCH + rbase + r] = b.z;
            g_ypk[3 * BATCH + rbase + r] = b.w;
        }
    }

    __syncthreads();
    if (i < BITD) g_su[i] = (double)ssu[i];
    if (i == 0) {
        float a = 0.f, b = 0.f;
#pragma unroll
        for (int w = 0; w < 16; w++) { a += swq[w]; b += sws[w]; }
        g_sum_usq = (double)a;
        g_s2      = (double)b;
    }
}

// --------------------------------------- scan: mismatch detection over N
__global__ void __launch_bounds__(256)
k_scan(const float* __restrict__ u, const float* __restrict__ U,
       const float* __restrict__ Y) {
    __shared__ unsigned sh[4 * BATCH];
    int t    = threadIdx.x;
    int lane = t & 31, warp = t >> 5;

    // stage packed batch table (2048 words) via uint4
#pragma unroll
    for (int i = 0; i < 2; i++)
        ((uint4*)sh)[t + i * 256] = ((const uint4*)g_ypk)[t + i * 256];

    int n     = blockIdx.x * 256 + t;
    int nbase = blockIdx.x * 256 + warp * 32;

    // warp-cooperative permuted pack of this warp's 32 training rows
    unsigned w0 = 0, w1 = 0, w2 = 0, w3 = 0;
    for (int r = 0; r < 32; r++) {
        int nr = nbase + r;
        if (nr >= NTRAIN) nr = NTRAIN - 1;
        uint4 b = pack_ballots(Y + (size_t)nr * NCLS, lane);
        if (lane == r) { w0 = b.x; w1 = b.y; w2 = b.z; w3 = b.w; }
    }
    __syncthreads();

    if (n >= NTRAIN) return;

    double corr = 0.0;
#pragma unroll 4
    for (int b0i = 0; b0i < BATCH; b0i += 8) {
        unsigned mna = sh[b0i]     & w0;
        unsigned mnb = sh[b0i + 4] & w0;
#pragma unroll
        for (int j = 1; j < 4; j++) {
            mna = min(mna, sh[b0i + j]     & w0);
            mnb = min(mnb, sh[b0i + 4 + j] & w0);
        }
        if (min(mna, mnb) == 0u) {
#pragma unroll 1
            for (int j = 0; j < 8; j++) {
                int b = b0i + j;
                unsigned r = (sh[b] & w0) | (sh[BATCH + b] & w1) |
                             (sh[2 * BATCH + b] & w2) | (sh[3 * BATCH + b] & w3);
                if (r == 0u)
                    corr += pair_term(b, u + b * BITD, U + (size_t)n * BITD);
            }
        }
    }
    if (corr != 0.0) atomicAdd(&g_corr, corr);
}

// --------------------------------------- U stats: flat float4 stream
__global__ void __launch_bounds__(256)
k_ust(const float* __restrict__ U) {
    __shared__ float scol[BITD + 8];
    int t    = threadIdx.x;
    int lane = t & 31, warp = t >> 5;

    const int nth = UST_BLOCKS * 256;                 // 131072 (mult of 16)
    int gid = blockIdx.x * 256 + t;
    const float4* U4 = (const float4*)U;
    const int total4 = NTRAIN * BITD / 4;             // 1.6M

    float c0 = 0.f, c1 = 0.f, c2 = 0.f, c3 = 0.f, sq = 0.f;
#pragma unroll 4
    for (int i = gid; i < total4; i += nth) {
        float4 v = U4[i];
        c0 += v.x; c1 += v.y; c2 += v.z; c3 += v.w;
        sq += v.x * v.x + v.y * v.y + v.z * v.z + v.w * v.w;
    }
    int cbase = (4 * gid) & (BITD - 1);
    c0 += __shfl_xor_sync(0xffffffffu, c0, 16);
    c1 += __shfl_xor_sync(0xffffffffu, c1, 16);
    c2 += __shfl_xor_sync(0xffffffffu, c2, 16);
    c3 += __shfl_xor_sync(0xffffffffu, c3, 16);
    sq = wred(sq);

    if (t < BITD + 8) scol[t] = 0.f;
    __syncthreads();
    if (lane < 16) {
        atomicAdd(&scol[cbase],     c0);
        atomicAdd(&scol[cbase + 1], c1);
        atomicAdd(&scol[cbase + 2], c2);
        atomicAdd(&scol[cbase + 3], c3);
    }
    if (lane == 0) scol[BITD + warp] = sq;
    __syncthreads();
    if (t < BITD) atomicAdd(&g_SU[t], (double)scol[t]);
    if (t == 0) {
        float s = 0.f;
#pragma unroll
        for (int w = 0; w < 8; w++) s += scol[BITD + w];
        atomicAdd(&g_SUsq, (double)s);
    }
}

// ----------------------- fix: buffer-update corrections (1 block, 512 thr)
__global__ void k_fix(const float* __restrict__ u, const int* __restrict__ ind,
                      const float* __restrict__ U, const float* __restrict__ Y) {
    __shared__ unsigned sh[4 * BATCH];
    __shared__ int      sind[BATCH];
    __shared__ float    scol[BITD];
    int t    = threadIdx.x;
    int lane = t & 31;

    sind[t] = ind[t];
#pragma unroll
    for (int j = 0; j < 4; j++) sh[t + j * BATCH] = g_ypk[t + j * BATCH];
    if (t < BITD) scol[t] = 0.f;
    __syncthreads();

    int  n = sind[t];
    bool last = true;
    for (int j = t + 1; j < BATCH; j++)
        if (sind[j] == n) { last = false; break; }

    double corr = 0.0; float dsq = 0.f;
    if (last) {
        unsigned m0 = sh[t],             m1 = sh[BATCH + t];
        unsigned m2 = sh[2 * BATCH + t], m3 = sh[3 * BATCH + t];
        // pack original Y row n with the SAME permutation: class c -> word
        // (c&3), bit (c>>2)
        const float* yr = Y + (size_t)n * NCLS;
        unsigned yn[4] = {0u, 0u, 0u, 0u};
#pragma unroll
        for (int c = 0; c < NCLS; c++)
            if (yr[c] != 0.f) yn[c & 3] |= 1u << (c >> 2);
        unsigned yn0 = yn[0], yn1 = yn[1], yn2 = yn[2], yn3 = yn[3];

        for (int b0i = 0; b0i < BATCH; b0i += 8) {
            unsigned mo = sh[b0i] & yn0;
            unsigned mn = sh[b0i] & m0;
#pragma unroll
            for (int j = 1; j < 8; j++) {
                mo = min(mo, sh[b0i + j] & yn0);
                mn = min(mn, sh[b0i + j] & m0);
            }
            if (min(mo, mn) == 0u) {
#pragma unroll 1
                for (int j = 0; j < 8; j++) {
                    int b = b0i + j;
                    unsigned ro = (sh[b] & yn0) | (sh[BATCH + b] & yn1) |
                                  (sh[2 * BATCH + b] & yn2) |
                                  (sh[3 * BATCH + b] & yn3);
                    if (ro == 0u)   // remove scan's old-data contribution
                        corr -= pair_term(b, u + b * BITD,
                                          U + (size_t)n * BITD);
                    unsigned rn = (sh[b] & m0) | (sh[BATCH + b] & m1) |
                                  (sh[2 * BATCH + b] & m2) |
                                  (sh[3 * BATCH + b] & m3);
                    if (rn == 0u)   // add updated-data contribution
                        corr += pair_term(b, u + b * BITD, u + t * BITD);
                }
            }
        }
        // SU / SUsq delta for the overwritten row
        const float* ur = u + t * BITD;
        const float* Ur = U + (size_t)n * BITD;
#pragma unroll
        for (int kk = 0; kk < BITD; kk++) {
            int k = (kk + t) & (BITD - 1);
            float a = ur[k], c = Ur[k];
            dsq += a * a - c * c;
            atomicAdd(&scol[k], a - c);
        }
    }
    if (corr != 0.0) atomicAdd(&g_corr, corr);
    dsq = wred(dsq);
    if (lane == 0 && dsq != 0.f) atomicAdd(&g_SUsq, (double)dsq);
    __syncthreads();
    if (t < BITD && scol[t] != 0.f) atomicAdd(&g_SU[t], (double)scol[t]);
}

// ---------------------------------------------------------- finalize
__global__ void k_final(float* __restrict__ out) {
    double dotsum = 0.0;
#pragma unroll
    for (int k = 0; k < BITD; k++) dotsum += g_su[k] * g_SU[k];
    double sum_dist = (double)NTRAIN * g_sum_usq
                    + (double)BATCH  * g_SUsq
                    - 2.0 * dotsum;
    double loss1 = (0.5 * sum_dist + g_corr)
                 / ((double)BATCH * (double)NTRAIN);
    double loss2 = 0.1 * g_s2 / ((double)BATCH * (double)BITD);
    out[0] = (float)(loss1 + loss2);
}

// ------------------------------------------------------------ launcher
extern "C" void kernel_launch(void* const* d_in, const int* in_sizes, int n_in,
                              void* d_out, int out_size) {
    const float* u   = (const float*)d_in[0];   // [512, 64]
    const float* y   = (const float*)d_in[1];   // [512, 100]
    const int*   ind = (const int*)  d_in[2];   // [512]
    const float* U   = (const float*)d_in[3];   // [100000, 64]
    const float* Y   = (const float*)d_in[4];   // [100000, 100]
    float* out = (float*)d_out;

    k_batch<<<1, BATCH>>>(u, y);
    k_scan<<<SCAN_BLOCKS, 256>>>(u, U, Y);
    k_ust<<<UST_BLOCKS, 256>>>(U);
    k_fix<<<1, BATCH>>>(u, ind, U, Y);
    k_final<<<1, 1>>>(out);
}

// round 5
// speedup vs baseline: 4.3640x; 4.3640x over previous
#include <cuda_runtime.h>
#include <cstdint>

#define BATCH    512
#define BITD     64
#define NCLS     100
#define NTRAIN   100000
#define MARGIN_F 128.0f

#define SCAN_BLOCKS 391          // ceil(100000/256)
#define UST_BLOCKS  512

// -------- device accumulators / scratch (no allocations allowed) --------
__device__ double   g_sum_usq;        // sum_b |u_b|^2
__device__ double   g_s2;             // sum |1 - sign(u)|
__device__ double   g_SUsq;           // sum_n |U_n|^2 (original U)
__device__ double   g_corr;           // hinge corrections over mismatch pairs
__device__ double   g_su[BITD];       // column sums of u
__device__ double   g_SU[BITD];       // column sums of U (original)
__device__ float    g_usq[BATCH];     // per-row |u_b|^2
__device__ __align__(16) unsigned g_ypk[4 * BATCH]; // packed labels [word][row]
__device__ float    g_fixdelta[BATCH * BITD];  // per-row column deltas (u-U)
__device__ float    g_fixdsq[BATCH];           // per-row |u|^2-|U|^2 delta

__device__ __forceinline__ float wred(float v) {
#pragma unroll
    for (int o = 16; o; o >>= 1) v += __shfl_xor_sync(0xffffffffu, v, o);
    return v;
}

// --------- rare path: exact pair term 0.5*(max(m-d,0) - d) --------------
// Serial FMA chain: identical FP-op order wherever compiled -> the
// add-then-subtract cancellation across k_scan/k_fix is bit-exact.
__device__ __noinline__ double pair_term(int b, const float* __restrict__ ur,
                                         const float* __restrict__ vr) {
    float dot = 0.f, vsq = 0.f;
#pragma unroll 16
    for (int k = 0; k < BITD; k++) {
        float a = ur[k], c = vr[k];
        dot = fmaf(a, c, dot);
        vsq = fmaf(c, c, vsq);
    }
    float d = g_usq[b] - 2.f * dot + vsq;
    d = fmaxf(d, 0.f);
    return 0.5 * ((double)fmaxf(MARGIN_F - d, 0.f) - (double)d);
}

// Warp-cooperative permuted pack: lane l<25 supplies classes 4l..4l+3.
// Class c maps to word (c&3), bit (c>>2); permutation-consistent everywhere;
// set intersection is permutation-invariant.
__device__ __forceinline__ uint4 pack_ballots(const float* __restrict__ row,
                                              int lane) {
    float4 v = make_float4(0.f, 0.f, 0.f, 0.f);
    if (lane < 25) v = ((const float4*)row)[lane];
    uint4 r;
    r.x = __ballot_sync(0xffffffffu, v.x != 0.f);
    r.y = __ballot_sync(0xffffffffu, v.y != 0.f);
    r.z = __ballot_sync(0xffffffffu, v.z != 0.f);
    r.w = __ballot_sync(0xffffffffu, v.w != 0.f);
    return r;
}

// ------------------------------------------------- batch stats + y pack
__global__ void k_batch(const float* __restrict__ u,
                        const float* __restrict__ y) {
    __shared__ float ssu[BITD + 16];      // columns + per-warp s2 partials
    __shared__ float susq[BATCH];         // per-row |u|^2
    int i    = threadIdx.x;               // 512 threads, 1 block
    int lane = i & 31, warp = i >> 5;

    if (i < BITD + 16) ssu[i] = 0.f;
    susq[i] = 0.f;
    if (i < BITD) g_SU[i] = 0.0;
    if (i == 0) { g_SUsq = 0.0; g_corr = 0.0; }
    __syncthreads();

    // flat float4 stream over u (32768 floats = 8192 float4), coalesced.
    // stride 512*4 floats = 2048 == 0 mod 64 -> columns fixed per thread.
    const float4* u4 = (const float4*)u;
    float c0 = 0.f, c1 = 0.f, c2 = 0.f, c3 = 0.f, s2 = 0.f;
#pragma unroll
    for (int jj = 0; jj < 16; jj++) {
        int f = i + jj * 512;             // float4 index; row = f>>4
        float4 v = u4[f];
        c0 += v.x; c1 += v.y; c2 += v.z; c3 += v.w;
        float q = v.x * v.x + v.y * v.y + v.z * v.z + v.w * v.w;
        s2 += ((v.x > 0.f) ? 0.f : ((v.x < 0.f) ? 2.f : 1.f))
            + ((v.y > 0.f) ? 0.f : ((v.y < 0.f) ? 2.f : 1.f))
            + ((v.z > 0.f) ? 0.f : ((v.z < 0.f) ? 2.f : 1.f))
            + ((v.w > 0.f) ? 0.f : ((v.w < 0.f) ? 2.f : 1.f));
        atomicAdd(&susq[f >> 4], q);
    }
    int cbase = (4 * i) & (BITD - 1);
    c0 += __shfl_xor_sync(0xffffffffu, c0, 16);
    c1 += __shfl_xor_sync(0xffffffffu, c1, 16);
    c2 += __shfl_xor_sync(0xffffffffu, c2, 16);
    c3 += __shfl_xor_sync(0xffffffffu, c3, 16);
    if (lane < 16) {
        atomicAdd(&ssu[cbase],     c0);
        atomicAdd(&ssu[cbase + 1], c1);
        atomicAdd(&ssu[cbase + 2], c2);
        atomicAdd(&ssu[cbase + 3], c3);
    }
    s2 = wred(s2);
    if (lane == 0) ssu[BITD + warp] = s2;

    // warp-cooperative permuted pack: warp w packs rows 32w..32w+31
    int rbase = warp * 32;
    for (int r = 0; r < 32; r++) {
        uint4 b = pack_ballots(y + (size_t)(rbase + r) * NCLS, lane);
        if (lane == r) {
            g_ypk[rbase + r]             = b.x;
            g_ypk[BATCH + rbase + r]     = b.y;
            g_ypk[2 * BATCH + rbase + r] = b.z;
            g_ypk[3 * BATCH + rbase + r] = b.w;
        }
    }

    __syncthreads();
    g_usq[i] = susq[i];
    if (i < BITD) g_su[i] = (double)ssu[i];
    if (i == 0) {
        float a = 0.f;
#pragma unroll
        for (int w = 0; w < 16; w++) a += ssu[BITD + w];
        g_s2 = (double)a;
        float q = 0.f;
        for (int r = 0; r < BATCH; r++) q += susq[r];
        g_sum_usq = (double)q;
    }
}

// --------------------------------------- scan: mismatch detection over N
__global__ void __launch_bounds__(256)
k_scan(const float* __restrict__ u, const float* __restrict__ U,
       const float* __restrict__ Y) {
    __shared__ unsigned sh[4 * BATCH];
    int t    = threadIdx.x;
    int lane = t & 31, warp = t >> 5;

#pragma unroll
    for (int i = 0; i < 2; i++)
        ((uint4*)sh)[t + i * 256] = ((const uint4*)g_ypk)[t + i * 256];

    int n     = blockIdx.x * 256 + t;
    int nbase = blockIdx.x * 256 + warp * 32;

    unsigned w0 = 0, w1 = 0, w2 = 0, w3 = 0;
    for (int r = 0; r < 32; r++) {
        int nr = nbase + r;
        if (nr >= NTRAIN) nr = NTRAIN - 1;
        uint4 b = pack_ballots(Y + (size_t)nr * NCLS, lane);
        if (lane == r) { w0 = b.x; w1 = b.y; w2 = b.z; w3 = b.w; }
    }
    __syncthreads();

    if (n >= NTRAIN) return;

    double corr = 0.0;
#pragma unroll 4
    for (int b0i = 0; b0i < BATCH; b0i += 8) {
        unsigned mna = sh[b0i]     & w0;
        unsigned mnb = sh[b0i + 4] & w0;
#pragma unroll
        for (int j = 1; j < 4; j++) {
            mna = min(mna, sh[b0i + j]     & w0);
            mnb = min(mnb, sh[b0i + 4 + j] & w0);
        }
        if (min(mna, mnb) == 0u) {
#pragma unroll 1
            for (int j = 0; j < 8; j++) {
                int b = b0i + j;
                unsigned r = (sh[b] & w0) | (sh[BATCH + b] & w1) |
                             (sh[2 * BATCH + b] & w2) | (sh[3 * BATCH + b] & w3);
                if (r == 0u)
                    corr += pair_term(b, u + b * BITD, U + (size_t)n * BITD);
            }
        }
    }
    if (corr != 0.0) atomicAdd(&g_corr, corr);
}

// --------------------------------------- U stats: flat float4 stream
__global__ void __launch_bounds__(256)
k_ust(const float* __restrict__ U) {
    __shared__ float scol[BITD + 8];
    int t    = threadIdx.x;
    int lane = t & 31, warp = t >> 5;

    const int nth = UST_BLOCKS * 256;                 // 131072
    int gid = blockIdx.x * 256 + t;
    const float4* U4 = (const float4*)U;
    const int total4 = NTRAIN * BITD / 4;             // 1.6M

    float c0 = 0.f, c1 = 0.f, c2 = 0.f, c3 = 0.f, sq = 0.f;
#pragma unroll 4
    for (int i = gid; i < total4; i += nth) {
        float4 v = U4[i];
        c0 += v.x; c1 += v.y; c2 += v.z; c3 += v.w;
        sq += v.x * v.x + v.y * v.y + v.z * v.z + v.w * v.w;
    }
    int cbase = (4 * gid) & (BITD - 1);
    c0 += __shfl_xor_sync(0xffffffffu, c0, 16);
    c1 += __shfl_xor_sync(0xffffffffu, c1, 16);
    c2 += __shfl_xor_sync(0xffffffffu, c2, 16);
    c3 += __shfl_xor_sync(0xffffffffu, c3, 16);
    sq = wred(sq);

    if (t < BITD + 8) scol[t] = 0.f;
    __syncthreads();
    if (lane < 16) {
        atomicAdd(&scol[cbase],     c0);
        atomicAdd(&scol[cbase + 1], c1);
        atomicAdd(&scol[cbase + 2], c2);
        atomicAdd(&scol[cbase + 3], c3);
    }
    if (lane == 0) scol[BITD + warp] = sq;
    __syncthreads();
    if (t < BITD) atomicAdd(&g_SU[t], (double)scol[t]);
    if (t == 0) {
        float s = 0.f;
#pragma unroll
        for (int w = 0; w < 8; w++) s += scol[BITD + w];
        atomicAdd(&g_SUsq, (double)s);
    }
}

// ------------- fix: buffer-update corrections, ONE BLOCK PER BATCH ROW
__global__ void __launch_bounds__(256)
k_fix(const float* __restrict__ u, const int* __restrict__ ind,
      const float* __restrict__ U, const float* __restrict__ Y) {
    __shared__ unsigned sh[4 * BATCH];
    __shared__ int      sind[BATCH];
    __shared__ unsigned yn4[4];
    __shared__ int      s_last;
    __shared__ float    sred[2];

    int i = blockIdx.x;                   // batch row owned by this block
    int t = threadIdx.x;                  // 256 threads
    int lane = t & 31, warp = t >> 5;

    sind[t]       = ind[t];
    sind[t + 256] = ind[t + 256];
#pragma unroll
    for (int j = 0; j < 2; j++)
        ((uint4*)sh)[t + j * 256] = ((const uint4*)g_ypk)[t + j * 256];
    if (t == 0) s_last = 1;
    __syncthreads();

    int n = sind[i];
    for (int j = i + 1 + t; j < BATCH; j += 256)
        if (sind[j] == n) s_last = 0;
    __syncthreads();
    bool last = (s_last != 0);

    // warp 0 packs original Y row n (permutation-consistent)
    if (warp == 0) {
        uint4 b = pack_ballots(Y + (size_t)n * NCLS, lane);
        if (lane == 0) { yn4[0] = b.x; yn4[1] = b.y; yn4[2] = b.z; yn4[3] = b.w; }
    }
    __syncthreads();

    if (last) {
        unsigned yn0 = yn4[0], yn1 = yn4[1], yn2 = yn4[2], yn3 = yn4[3];
        unsigned m0 = sh[i],             m1 = sh[BATCH + i];
        unsigned m2 = sh[2 * BATCH + i], m3 = sh[3 * BATCH + i];
        double corr = 0.0;
#pragma unroll
        for (int bb = 0; bb < 2; bb++) {
            int b = t + bb * 256;
            unsigned ro = (sh[b] & yn0) | (sh[BATCH + b] & yn1) |
                          (sh[2 * BATCH + b] & yn2) | (sh[3 * BATCH + b] & yn3);
            if (ro == 0u)   // remove scan's old-data contribution
                corr -= pair_term(b, u + b * BITD, U + (size_t)n * BITD);
            unsigned rn = (sh[b] & m0) | (sh[BATCH + b] & m1) |
                          (sh[2 * BATCH + b] & m2) | (sh[3 * BATCH + b] & m3);
            if (rn == 0u)   // add updated-data contribution
                corr += pair_term(b, u + b * BITD, u + i * BITD);
        }
        if (corr != 0.0) atomicAdd(&g_corr, corr);
    }

    // staging: per-row column deltas and |u|^2-|U|^2 delta (zeros if !last)
    float dsq = 0.f;
    if (t < BITD) {
        float a = 0.f, c = 0.f;
        if (last) {
            a = u[i * BITD + t];
            c = U[(size_t)n * BITD + t];
        }
        g_fixdelta[i * BITD + t] = a - c;
        dsq = a * a - c * c;
    }
    if (t < BITD) {
        dsq = wred(dsq);
        if (lane == 0) sred[warp] = dsq;
    }
    __syncthreads();
    if (t == 0) g_fixdsq[i] = sred[0] + sred[1];
}

// ---------------------------------------------------------- finalize
__global__ void k_final(float* __restrict__ out) {
    __shared__ double sdot[BITD];
    __shared__ double sdsq[BITD];
    int t = threadIdx.x;                  // 64 threads

    double d = 0.0;
#pragma unroll 4
    for (int i = 0; i < BATCH; i++) d += (double)g_fixdelta[i * BITD + t];
    double colsum = g_SU[t] + d;
    sdot[t] = g_su[t] * colsum;

    double q = 0.0;
#pragma unroll
    for (int i = t; i < BATCH; i += BITD) q += (double)g_fixdsq[i];
    sdsq[t] = q;
    __syncthreads();

    if (t == 0) {
        double dotsum = 0.0, dq = 0.0;
#pragma unroll
        for (int k = 0; k < BITD; k++) { dotsum += sdot[k]; dq += sdsq[k]; }
        double SUsq = g_SUsq + dq;
        double sum_dist = (double)NTRAIN * g_sum_usq
                        + (double)BATCH  * SUsq
                        - 2.0 * dotsum;
        double loss1 = (0.5 * sum_dist + g_corr)
                     / ((double)BATCH * (double)NTRAIN);
        double loss2 = 0.1 * g_s2 / ((double)BATCH * (double)BITD);
        out[0] = (float)(loss1 + loss2);
    }
}

// ------------------------------------------------------------ launcher
extern "C" void kernel_launch(void* const* d_in, const int* in_sizes, int n_in,
                              void* d_out, int out_size) {
    const float* u   = (const float*)d_in[0];   // [512, 64]
    const float* y   = (const float*)d_in[1];   // [512, 100]
    const int*   ind = (const int*)  d_in[2];   // [512]
    const float* U   = (const float*)d_in[3];   // [100000, 64]
    const float* Y   = (const float*)d_in[4];   // [100000, 100]
    float* out = (float*)d_out;

    k_batch<<<1, BATCH>>>(u, y);
    k_scan<<<SCAN_BLOCKS, 256>>>(u, U, Y);
    k_ust<<<UST_BLOCKS, 256>>>(U);
    k_fix<<<BATCH, 256>>>(u, ind, U, Y);
    k_final<<<1, BITD>>>(out);
}

// round 6
// speedup vs baseline: 6.4611x; 1.4805x over previous
#include <cuda_runtime.h>
#include <cstdint>

#define BATCH    512
#define BITD     64
#define NCLS     100
#define NTRAIN   100000
#define MARGIN_F 128.0f

#define SCAN_BLOCKS 391          // ceil(100000/256)
#define UST_BLOCKS  512
#define FIX_BLOCKS  512
#define MEGA_BLOCKS (SCAN_BLOCKS + UST_BLOCKS + FIX_BLOCKS)

// -------- device accumulators / scratch (no allocations allowed) --------
__device__ double   g_sum_usq;        // sum_b |u_b|^2
__device__ double   g_s2;             // sum |1 - sign(u)|
__device__ double   g_SUsq;           // sum_n |U_n|^2 (original U)
__device__ double   g_corr;           // hinge corrections over mismatch pairs
__device__ double   g_su[BITD];       // column sums of u
__device__ double   g_SU[BITD];       // column sums of U (original)
__device__ float    g_usq[BATCH];     // per-row |u_b|^2
__device__ __align__(16) unsigned g_ypk[4 * BATCH];      // packed labels [word][row]
__device__ __align__(16) float    g_fixdelta[BATCH * BITD]; // per-row col deltas
__device__ float    g_fixdsq[BATCH];  // per-row |u|^2-|U|^2 delta

__device__ __forceinline__ float wred(float v) {
#pragma unroll
    for (int o = 16; o; o >>= 1) v += __shfl_xor_sync(0xffffffffu, v, o);
    return v;
}
__device__ __forceinline__ double wredd(double v) {
#pragma unroll
    for (int o = 16; o; o >>= 1) v += __shfl_xor_sync(0xffffffffu, v, o);
    return v;
}

// --------- rare path: exact pair term 0.5*(max(m-d,0) - d) --------------
// Serial FMA chain: identical FP-op order wherever compiled -> the
// add-then-subtract cancellation across scan/fix roles is bit-exact.
__device__ __noinline__ double pair_term(int b, const float* __restrict__ ur,
                                         const float* __restrict__ vr) {
    float dot = 0.f, vsq = 0.f;
#pragma unroll 16
    for (int k = 0; k < BITD; k++) {
        float a = ur[k], c = vr[k];
        dot = fmaf(a, c, dot);
        vsq = fmaf(c, c, vsq);
    }
    float d = g_usq[b] - 2.f * dot + vsq;
    d = fmaxf(d, 0.f);
    return 0.5 * ((double)fmaxf(MARGIN_F - d, 0.f) - (double)d);
}

// Warp-cooperative permuted pack: lane l<25 supplies classes 4l..4l+3.
// Class c maps to word (c&3), bit (c>>2); consistent everywhere; set
// intersection is permutation-invariant.
__device__ __forceinline__ uint4 pack_ballots(const float* __restrict__ row,
                                              int lane) {
    float4 v = make_float4(0.f, 0.f, 0.f, 0.f);
    if (lane < 25) v = ((const float4*)row)[lane];
    uint4 r;
    r.x = __ballot_sync(0xffffffffu, v.x != 0.f);
    r.y = __ballot_sync(0xffffffffu, v.y != 0.f);
    r.z = __ballot_sync(0xffffffffu, v.z != 0.f);
    r.w = __ballot_sync(0xffffffffu, v.w != 0.f);
    return r;
}

// ------------------------------------------------- batch stats + y pack
__global__ void k_batch(const float* __restrict__ u,
                        const float* __restrict__ y) {
    __shared__ float ssu[BITD + 32];      // cols + [64..80) s2 + [80..96) usq
    __shared__ float susq[BATCH];         // per-row |u|^2
    int i    = threadIdx.x;               // 512 threads, 1 block
    int lane = i & 31, warp = i >> 5;

    if (i < BITD + 32) ssu[i] = 0.f;
    susq[i] = 0.f;
    if (i < BITD) g_SU[i] = 0.0;
    if (i == 0) { g_SUsq = 0.0; g_corr = 0.0; }
    __syncthreads();

    // flat float4 stream over u (8192 float4), coalesced; stride 2048 floats
    // == 0 mod 64 -> columns fixed per thread.
    const float4* u4 = (const float4*)u;
    float c0 = 0.f, c1 = 0.f, c2 = 0.f, c3 = 0.f, s2 = 0.f;
#pragma unroll
    for (int jj = 0; jj < 16; jj++) {
        int f = i + jj * 512;             // float4 index; row = f>>4
        float4 v = u4[f];
        c0 += v.x; c1 += v.y; c2 += v.z; c3 += v.w;
        float q = v.x * v.x + v.y * v.y + v.z * v.z + v.w * v.w;
        s2 += ((v.x > 0.f) ? 0.f : ((v.x < 0.f) ? 2.f : 1.f))
            + ((v.y > 0.f) ? 0.f : ((v.y < 0.f) ? 2.f : 1.f))
            + ((v.z > 0.f) ? 0.f : ((v.z < 0.f) ? 2.f : 1.f))
            + ((v.w > 0.f) ? 0.f : ((v.w < 0.f) ? 2.f : 1.f));
        atomicAdd(&susq[f >> 4], q);
    }
    int cbase = (4 * i) & (BITD - 1);
    c0 += __shfl_xor_sync(0xffffffffu, c0, 16);
    c1 += __shfl_xor_sync(0xffffffffu, c1, 16);
    c2 += __shfl_xor_sync(0xffffffffu, c2, 16);
    c3 += __shfl_xor_sync(0xffffffffu, c3, 16);
    if (lane < 16) {
        atomicAdd(&ssu[cbase],     c0);
        atomicAdd(&ssu[cbase + 1], c1);
        atomicAdd(&ssu[cbase + 2], c2);
        atomicAdd(&ssu[cbase + 3], c3);
    }
    s2 = wred(s2);
    if (lane == 0) ssu[BITD + warp] = s2;

    // warp-cooperative permuted pack: warp w packs rows 32w..32w+31
    int rbase = warp * 32;
    for (int r = 0; r < 32; r++) {
        uint4 b = pack_ballots(y + (size_t)(rbase + r) * NCLS, lane);
        if (lane == r) {
            g_ypk[rbase + r]             = b.x;
            g_ypk[BATCH + rbase + r]     = b.y;
            g_ypk[2 * BATCH + rbase + r] = b.z;
            g_ypk[3 * BATCH + rbase + r] = b.w;
        }
    }
    __syncthreads();

    float myq = susq[i];
    g_usq[i] = myq;
    float qr = wred(myq);
    if (lane == 0) ssu[BITD + 16 + warp] = qr;
    if (i < BITD) g_su[i] = (double)ssu[i];
    __syncthreads();
    if (i == 0) {
        float a = 0.f, q = 0.f;
#pragma unroll
        for (int w = 0; w < 16; w++) { a += ssu[BITD + w]; q += ssu[BITD + 16 + w]; }
        g_s2      = (double)a;
        g_sum_usq = (double)q;
    }
}

// ------------- mega kernel: scan role + U-stats role + fix role ----------
__global__ void __launch_bounds__(256)
k_mega(const float* __restrict__ u, const int* __restrict__ ind,
       const float* __restrict__ U, const float* __restrict__ Y) {
    __shared__ __align__(16) unsigned sh[4 * BATCH];  // 8KB
    __shared__ int      sind[BATCH];
    __shared__ float    scol[BITD + 8];
    __shared__ unsigned yn4[4];
    __shared__ int      s_last;
    __shared__ float    sred[2];

    int t    = threadIdx.x;
    int lane = t & 31, warp = t >> 5;

    if (blockIdx.x < SCAN_BLOCKS) {
        // ================= scan role =====================================
#pragma unroll
        for (int i = 0; i < 2; i++)
            ((uint4*)sh)[t + i * 256] = ((const uint4*)g_ypk)[t + i * 256];

        int n     = blockIdx.x * 256 + t;
        int nbase = blockIdx.x * 256 + warp * 32;

        unsigned w0 = 0, w1 = 0, w2 = 0, w3 = 0;
        for (int r = 0; r < 32; r++) {
            int nr = nbase + r;
            if (nr >= NTRAIN) nr = NTRAIN - 1;
            uint4 b = pack_ballots(Y + (size_t)nr * NCLS, lane);
            if (lane == r) { w0 = b.x; w1 = b.y; w2 = b.z; w3 = b.w; }
        }
        __syncthreads();

        if (n >= NTRAIN) return;

        const uint4* sh4 = (const uint4*)sh;          // word-0 table as uint4
        double corr = 0.0;
#pragma unroll 4
        for (int b0i = 0; b0i < BATCH; b0i += 8) {
            uint4 pa = sh4[b0i >> 2];
            uint4 pb = sh4[(b0i >> 2) + 1];
            unsigned mna = min(min(pa.x & w0, pa.y & w0),
                               min(pa.z & w0, pa.w & w0));
            unsigned mnb = min(min(pb.x & w0, pb.y & w0),
                               min(pb.z & w0, pb.w & w0));
            if (min(mna, mnb) == 0u) {
#pragma unroll 1
                for (int j = 0; j < 8; j++) {
                    int b = b0i + j;
                    unsigned r = (sh[b] & w0) | (sh[BATCH + b] & w1) |
                                 (sh[2 * BATCH + b] & w2) |
                                 (sh[3 * BATCH + b] & w3);
                    if (r == 0u)
                        corr += pair_term(b, u + b * BITD,
                                          U + (size_t)n * BITD);
                }
            }
        }
        if (corr != 0.0) atomicAdd(&g_corr, corr);
    } else if (blockIdx.x < SCAN_BLOCKS + UST_BLOCKS) {
        // ================= U stats role ==================================
        const int nth = UST_BLOCKS * 256;                 // 131072
        int gid = (blockIdx.x - SCAN_BLOCKS) * 256 + t;
        const float4* U4 = (const float4*)U;
        const int total4 = NTRAIN * BITD / 4;             // 1.6M

        float c0 = 0.f, c1 = 0.f, c2 = 0.f, c3 = 0.f, sq = 0.f;
#pragma unroll 4
        for (int i = gid; i < total4; i += nth) {
            float4 v = U4[i];
            c0 += v.x; c1 += v.y; c2 += v.z; c3 += v.w;
            sq += v.x * v.x + v.y * v.y + v.z * v.z + v.w * v.w;
        }
        int cbase = (4 * gid) & (BITD - 1);
        c0 += __shfl_xor_sync(0xffffffffu, c0, 16);
        c1 += __shfl_xor_sync(0xffffffffu, c1, 16);
        c2 += __shfl_xor_sync(0xffffffffu, c2, 16);
        c3 += __shfl_xor_sync(0xffffffffu, c3, 16);
        sq = wred(sq);

        if (t < BITD + 8) scol[t] = 0.f;
        __syncthreads();
        if (lane < 16) {
            atomicAdd(&scol[cbase],     c0);
            atomicAdd(&scol[cbase + 1], c1);
            atomicAdd(&scol[cbase + 2], c2);
            atomicAdd(&scol[cbase + 3], c3);
        }
        if (lane == 0) scol[BITD + warp] = sq;
        __syncthreads();
        if (t < BITD) atomicAdd(&g_SU[t], (double)scol[t]);
        if (t == 0) {
            float s = 0.f;
#pragma unroll
            for (int w = 0; w < 8; w++) s += scol[BITD + w];
            atomicAdd(&g_SUsq, (double)s);
        }
    } else {
        // ================= fix role: one block per batch row =============
        int i = blockIdx.x - SCAN_BLOCKS - UST_BLOCKS;    // 0..511

        sind[t]       = ind[t];
        sind[t + 256] = ind[t + 256];
#pragma unroll
        for (int j = 0; j < 2; j++)
            ((uint4*)sh)[t + j * 256] = ((const uint4*)g_ypk)[t + j * 256];
        if (t == 0) s_last = 1;
        __syncthreads();

        int n = sind[i];
        for (int j = i + 1 + t; j < BATCH; j += 256)
            if (sind[j] == n) s_last = 0;
        __syncthreads();
        bool last = (s_last != 0);

        if (warp == 0) {
            uint4 b = pack_ballots(Y + (size_t)n * NCLS, lane);
            if (lane == 0) { yn4[0] = b.x; yn4[1] = b.y;
                             yn4[2] = b.z; yn4[3] = b.w; }
        }
        __syncthreads();

        if (last) {
            unsigned yn0 = yn4[0], yn1 = yn4[1], yn2 = yn4[2], yn3 = yn4[3];
            unsigned m0 = sh[i],             m1 = sh[BATCH + i];
            unsigned m2 = sh[2 * BATCH + i], m3 = sh[3 * BATCH + i];
            double corr = 0.0;
#pragma unroll
            for (int bb = 0; bb < 2; bb++) {
                int b = t + bb * 256;
                unsigned ro = (sh[b] & yn0) | (sh[BATCH + b] & yn1) |
                              (sh[2 * BATCH + b] & yn2) |
                              (sh[3 * BATCH + b] & yn3);
                if (ro == 0u)   // remove scan's old-data contribution
                    corr -= pair_term(b, u + b * BITD, U + (size_t)n * BITD);
                unsigned rn = (sh[b] & m0) | (sh[BATCH + b] & m1) |
                              (sh[2 * BATCH + b] & m2) |
                              (sh[3 * BATCH + b] & m3);
                if (rn == 0u)   // add updated-data contribution
                    corr += pair_term(b, u + b * BITD, u + i * BITD);
            }
            if (corr != 0.0) atomicAdd(&g_corr, corr);
        }

        // staging: per-row column deltas and |u|^2-|U|^2 delta (0 if !last)
        float dsq = 0.f;
        if (t < BITD) {
            float a = 0.f, c = 0.f;
            if (last) {
                a = u[i * BITD + t];
                c = U[(size_t)n * BITD + t];
            }
            g_fixdelta[i * BITD + t] = a - c;
            dsq = a * a - c * c;
            dsq = wred(dsq);
            if (lane == 0) sred[warp] = dsq;
        }
        __syncthreads();
        if (t == 0) g_fixdsq[i] = sred[0] + sred[1];
    }
}

// ---------------------------------------------------------- finalize
__global__ void __launch_bounds__(512)
k_final(float* __restrict__ out) {
    __shared__ double scol[BITD];
    __shared__ double sterm[BITD];
    __shared__ double sdq[16];
    int t    = threadIdx.x;               // 512 threads
    int lane = t & 31, warp = t >> 5;

    if (t < BITD) scol[t] = 0.0;
    __syncthreads();

    // flat float4 reduction of g_fixdelta (8192 float4), columns fixed
    const float4* fd4 = (const float4*)g_fixdelta;
    double c0 = 0.0, c1 = 0.0, c2 = 0.0, c3 = 0.0;
#pragma unroll
    for (int j = 0; j < 16; j++) {
        float4 v = fd4[t + j * 512];
        c0 += (double)v.x; c1 += (double)v.y;
        c2 += (double)v.z; c3 += (double)v.w;
    }
    int cbase = (4 * t) & (BITD - 1);
    c0 += __shfl_xor_sync(0xffffffffu, c0, 16);
    c1 += __shfl_xor_sync(0xffffffffu, c1, 16);
    c2 += __shfl_xor_sync(0xffffffffu, c2, 16);
    c3 += __shfl_xor_sync(0xffffffffu, c3, 16);
    if (lane < 16) {
        atomicAdd(&scol[cbase],     c0);
        atomicAdd(&scol[cbase + 1], c1);
        atomicAdd(&scol[cbase + 2], c2);
        atomicAdd(&scol[cbase + 3], c3);
    }

    double q = wredd((double)g_fixdsq[t]);
    if (lane == 0) sdq[warp] = q;
    __syncthreads();

    if (t < BITD) sterm[t] = g_su[t] * (g_SU[t] + scol[t]);
    __syncthreads();

    if (t == 0) {
        double dotsum = 0.0, dq = 0.0;
#pragma unroll
        for (int k = 0; k < BITD; k++) dotsum += sterm[k];
#pragma unroll
        for (int w = 0; w < 16; w++) dq += sdq[w];
        double SUsq = g_SUsq + dq;
        double sum_dist = (double)NTRAIN * g_sum_usq
                        + (double)BATCH  * SUsq
                        - 2.0 * dotsum;
        double loss1 = (0.5 * sum_dist + g_corr)
                     / ((double)BATCH * (double)NTRAIN);
        double loss2 = 0.1 * g_s2 / ((double)BATCH * (double)BITD);
        out[0] = (float)(loss1 + loss2);
    }
}

// ------------------------------------------------------------ launcher
extern "C" void kernel_launch(void* const* d_in, const int* in_sizes, int n_in,
                              void* d_out, int out_size) {
    const float* u   = (const float*)d_in[0];   // [512, 64]
    const float* y   = (const float*)d_in[1];   // [512, 100]
    const int*   ind = (const int*)  d_in[2];   // [512]
    const float* U   = (const float*)d_in[3];   // [100000, 64]
    const float* Y   = (const float*)d_in[4];   // [100000, 100]
    float* out = (float*)d_out;

    k_batch<<<1, BATCH>>>(u, y);
    k_mega<<<MEGA_BLOCKS, 256>>>(u, ind, U, Y);
    k_final<<<1, 512>>>(out);
}

// round 7
// speedup vs baseline: 9.5812x; 1.4829x over previous
#include <cuda_runtime.h>
#include <cstdint>

#define BATCH    512
#define BITD     64
#define NCLS     100
#define NTRAIN   100000
#define MARGIN_F 128.0f

#define BATCH_BLOCKS 128         // 4 rows per block
#define SCAN_BLOCKS  391         // ceil(100000/256)
#define UST_BLOCKS   512
#define FIX_BLOCKS   512
#define MEGA_BLOCKS  (SCAN_BLOCKS + UST_BLOCKS + FIX_BLOCKS)

// -------- device accumulators / scratch (no allocations allowed) --------
__device__ double   g_SUsq;           // sum_n |U'_n|^2 (ust + fix deltas)
__device__ double   g_corr;           // hinge corrections over mismatch pairs
__device__ double   g_SU[BITD];       // column sums of U' (ust + fix deltas)
__device__ float    g_usq[BATCH];     // per-row |u_b|^2
__device__ __align__(16) unsigned g_ypk[4 * BATCH];   // packed labels [word][row]
__device__ __align__(16) float g_supart[BATCH_BLOCKS * BITD]; // u col partials
__device__ float    g_uqpart[BATCH_BLOCKS];  // per-block sum |u|^2 partials
__device__ float    g_s2part[BATCH_BLOCKS];  // per-block s2 partials
__device__ unsigned g_done;           // mega-block completion counter

__device__ __forceinline__ float wred(float v) {
#pragma unroll
    for (int o = 16; o; o >>= 1) v += __shfl_xor_sync(0xffffffffu, v, o);
    return v;
}

// --------- rare path: exact pair term 0.5*(max(m-d,0) - d) --------------
// Serial FMA chain: identical FP-op order wherever compiled -> the
// add-then-subtract cancellation across scan/fix roles is bit-exact.
__device__ __noinline__ double pair_term(int b, const float* __restrict__ ur,
                                         const float* __restrict__ vr) {
    float dot = 0.f, vsq = 0.f;
#pragma unroll 16
    for (int k = 0; k < BITD; k++) {
        float a = ur[k], c = vr[k];
        dot = fmaf(a, c, dot);
        vsq = fmaf(c, c, vsq);
    }
    float d = g_usq[b] - 2.f * dot + vsq;
    d = fmaxf(d, 0.f);
    return 0.5 * ((double)fmaxf(MARGIN_F - d, 0.f) - (double)d);
}

// Warp-cooperative permuted pack: lane l<25 supplies classes 4l..4l+3.
// Class c -> word (c&3), bit (c>>2); consistent everywhere; set
// intersection is permutation-invariant.
__device__ __forceinline__ uint4 pack_ballots(const float* __restrict__ row,
                                              int lane) {
    float4 v = make_float4(0.f, 0.f, 0.f, 0.f);
    if (lane < 25) v = ((const float4*)row)[lane];
    uint4 r;
    r.x = __ballot_sync(0xffffffffu, v.x != 0.f);
    r.y = __ballot_sync(0xffffffffu, v.y != 0.f);
    r.z = __ballot_sync(0xffffffffu, v.z != 0.f);
    r.w = __ballot_sync(0xffffffffu, v.w != 0.f);
    return r;
}

// ------------- batch stats + y pack: 128 blocks, 4 rows per block --------
__global__ void __launch_bounds__(256)
k_batch(const float* __restrict__ u, const float* __restrict__ y) {
    __shared__ float scol[BITD];
    __shared__ float sv[8];               // [0..4) usq, [4..8) s2 per warp
    int t    = threadIdx.x;
    int lane = t & 31, warp = t >> 5;
    int row  = blockIdx.x * 4 + warp;     // 0..511

    if (t < BITD) scol[t] = 0.f;
    if (blockIdx.x == 0) {                // zero global accumulators
        if (t < BITD) g_SU[t] = 0.0;
        if (t == 0) { g_SUsq = 0.0; g_corr = 0.0; g_done = 0u; }
    }
    __syncthreads();

    // u stats: lane owns columns 2*lane, 2*lane+1 of its row
    float2 v = ((const float2*)(u + row * BITD))[lane];
    float usq = v.x * v.x + v.y * v.y;
    float s2  = ((v.x > 0.f) ? 0.f : ((v.x < 0.f) ? 2.f : 1.f))
              + ((v.y > 0.f) ? 0.f : ((v.y < 0.f) ? 2.f : 1.f));
    atomicAdd(&scol[2 * lane],     v.x);  // 4-way conflict max (4 warps)
    atomicAdd(&scol[2 * lane + 1], v.y);
    float usqr = wred(usq);
    float s2r  = wred(s2);
    if (lane == 0) { g_usq[row] = usqr; sv[warp] = usqr; sv[4 + warp] = s2r; }

    // warp packs its row's labels
    uint4 b = pack_ballots(y + (size_t)row * NCLS, lane);
    if (lane == 0) {
        g_ypk[row]             = b.x;
        g_ypk[BATCH + row]     = b.y;
        g_ypk[2 * BATCH + row] = b.z;
        g_ypk[3 * BATCH + row] = b.w;
    }
    __syncthreads();

    if (t < BITD) g_supart[blockIdx.x * BITD + t] = scol[t];
    if (t == 0) {
        g_uqpart[blockIdx.x] = sv[0] + sv[1] + sv[2] + sv[3];
        g_s2part[blockIdx.x] = sv[4] + sv[5] + sv[6] + sv[7];
    }
}

// ------------- mega kernel: scan + U-stats + fix + finalize tail ---------
__global__ void __launch_bounds__(256)
k_mega(const float* __restrict__ u, const int* __restrict__ ind,
       const float* __restrict__ U, const float* __restrict__ Y,
       float* __restrict__ out) {
    __shared__ __align__(16) unsigned sh[4 * BATCH];  // 8KB
    __shared__ int      sind[BATCH];
    __shared__ float    scol[BITD + 8];
    __shared__ unsigned yn4[4];
    __shared__ int      s_last;
    __shared__ int      s_flag;

    int t    = threadIdx.x;
    int lane = t & 31, warp = t >> 5;

    if (blockIdx.x < SCAN_BLOCKS) {
        // ================= scan role =====================================
#pragma unroll
        for (int i = 0; i < 2; i++)
            ((uint4*)sh)[t + i * 256] = ((const uint4*)g_ypk)[t + i * 256];

        int n     = blockIdx.x * 256 + t;
        int nbase = blockIdx.x * 256 + warp * 32;

        unsigned w0 = 0, w1 = 0, w2 = 0, w3 = 0;
        for (int r = 0; r < 32; r++) {
            int nr = nbase + r;
            if (nr >= NTRAIN) nr = NTRAIN - 1;
            uint4 b = pack_ballots(Y + (size_t)nr * NCLS, lane);
            if (lane == r) { w0 = b.x; w1 = b.y; w2 = b.z; w3 = b.w; }
        }
        __syncthreads();

        if (n < NTRAIN) {
            const uint4* sh4 = (const uint4*)sh;      // word-0 table as uint4
            double corr = 0.0;
#pragma unroll 4
            for (int b0i = 0; b0i < BATCH; b0i += 8) {
                uint4 pa = sh4[b0i >> 2];
                uint4 pb = sh4[(b0i >> 2) + 1];
                unsigned mna = min(min(pa.x & w0, pa.y & w0),
                                   min(pa.z & w0, pa.w & w0));
                unsigned mnb = min(min(pb.x & w0, pb.y & w0),
                                   min(pb.z & w0, pb.w & w0));
                if (min(mna, mnb) == 0u) {
#pragma unroll 1
                    for (int j = 0; j < 8; j++) {
                        int b = b0i + j;
                        unsigned r = (sh[b] & w0) | (sh[BATCH + b] & w1) |
                                     (sh[2 * BATCH + b] & w2) |
                                     (sh[3 * BATCH + b] & w3);
                        if (r == 0u)
                            corr += pair_term(b, u + b * BITD,
                                              U + (size_t)n * BITD);
                    }
                }
            }
            if (corr != 0.0) atomicAdd(&g_corr, corr);
        }
    } else if (blockIdx.x < SCAN_BLOCKS + UST_BLOCKS) {
        // ================= U stats role ==================================
        const int nth = UST_BLOCKS * 256;                 // 131072
        int gid = (blockIdx.x - SCAN_BLOCKS) * 256 + t;
        const float4* U4 = (const float4*)U;
        const int total4 = NTRAIN * BITD / 4;             // 1.6M

        float c0 = 0.f, c1 = 0.f, c2 = 0.f, c3 = 0.f, sq = 0.f;
#pragma unroll 4
        for (int i = gid; i < total4; i += nth) {
            float4 v = U4[i];
            c0 += v.x; c1 += v.y; c2 += v.z; c3 += v.w;
            sq += v.x * v.x + v.y * v.y + v.z * v.z + v.w * v.w;
        }
        int cbase = (4 * gid) & (BITD - 1);
        c0 += __shfl_xor_sync(0xffffffffu, c0, 16);
        c1 += __shfl_xor_sync(0xffffffffu, c1, 16);
        c2 += __shfl_xor_sync(0xffffffffu, c2, 16);
        c3 += __shfl_xor_sync(0xffffffffu, c3, 16);
        sq = wred(sq);

        if (t < BITD + 8) scol[t] = 0.f;
        __syncthreads();
        if (lane < 16) {
            atomicAdd(&scol[cbase],     c0);
            atomicAdd(&scol[cbase + 1], c1);
            atomicAdd(&scol[cbase + 2], c2);
            atomicAdd(&scol[cbase + 3], c3);
        }
        if (lane == 0) scol[BITD + warp] = sq;
        __syncthreads();
        if (t < BITD) atomicAdd(&g_SU[t], (double)scol[t]);
        if (t == 0) {
            float s = 0.f;
#pragma unroll
            for (int w = 0; w < 8; w++) s += scol[BITD + w];
            atomicAdd(&g_SUsq, (double)s);
        }
    } else {
        // ================= fix role: one block per batch row =============
        int i = blockIdx.x - SCAN_BLOCKS - UST_BLOCKS;    // 0..511

        sind[t]       = ind[t];
        sind[t + 256] = ind[t + 256];
#pragma unroll
        for (int j = 0; j < 2; j++)
            ((uint4*)sh)[t + j * 256] = ((const uint4*)g_ypk)[t + j * 256];
        if (t == 0) s_last = 1;
        __syncthreads();

        int n = sind[i];
        for (int j = i + 1 + t; j < BATCH; j += 256)
            if (sind[j] == n) s_last = 0;
        __syncthreads();

        if (s_last) {
            if (warp == 0) {
                uint4 b = pack_ballots(Y + (size_t)n * NCLS, lane);
                if (lane == 0) { yn4[0] = b.x; yn4[1] = b.y;
                                 yn4[2] = b.z; yn4[3] = b.w; }
            }
            __syncthreads();

            unsigned yn0 = yn4[0], yn1 = yn4[1], yn2 = yn4[2], yn3 = yn4[3];
            unsigned m0 = sh[i],             m1 = sh[BATCH + i];
            unsigned m2 = sh[2 * BATCH + i], m3 = sh[3 * BATCH + i];
            double corr = 0.0;
#pragma unroll
            for (int bb = 0; bb < 2; bb++) {
                int b = t + bb * 256;
                unsigned ro = (sh[b] & yn0) | (sh[BATCH + b] & yn1) |
                              (sh[2 * BATCH + b] & yn2) |
                              (sh[3 * BATCH + b] & yn3);
                if (ro == 0u)   // remove scan's old-data contribution
                    corr -= pair_term(b, u + b * BITD, U + (size_t)n * BITD);
                unsigned rn = (sh[b] & m0) | (sh[BATCH + b] & m1) |
                              (sh[2 * BATCH + b] & m2) |
                              (sh[3 * BATCH + b] & m3);
                if (rn == 0u)   // add updated-data contribution
                    corr += pair_term(b, u + b * BITD, u + i * BITD);
            }
            if (corr != 0.0) atomicAdd(&g_corr, corr);

            // SU / SUsq deltas for the overwritten row (direct atomics)
            float dsq = 0.f;
            if (t < BITD) {
                float a = u[i * BITD + t];
                float c = U[(size_t)n * BITD + t];
                atomicAdd(&g_SU[t], (double)(a - c));
                dsq = a * a - c * c;
                dsq = wred(dsq);
                if (lane == 0) atomicAdd(&g_SUsq, (double)dsq);
            }
        }
    }

    // ================= finalize tail: last block to finish ===============
    __threadfence();
    __syncthreads();
    if (t == 0)
        s_flag = (atomicAdd(&g_done, 1u) == MEGA_BLOCKS - 1) ? 1 : 0;
    __syncthreads();
    if (!s_flag) return;
    __threadfence();

    __shared__ double sterm[BITD];
    __shared__ float  sparts[8];          // [0..4) usq, [4..8) s2

    // su[k] from 128 batch partials, dotted with completed SU[k]
    if (t < BITD) {
        double s = 0.0;
#pragma unroll 8
        for (int i = 0; i < BATCH_BLOCKS; i++)
            s += (double)g_supart[i * BITD + t];
        sterm[t] = s * g_SU[t];
    }
    // sum_usq / s2 from 128 partials (warps 0..3 cover them)
    if (t < BATCH_BLOCKS) {
        float q = wred(g_uqpart[t]);
        float a = wred(g_s2part[t]);
        if (lane == 0) { sparts[warp] = q; sparts[4 + warp] = a; }
    }
    __syncthreads();

    if (t == 0) {
        double dotsum = 0.0;
#pragma unroll
        for (int k = 0; k < BITD; k++) dotsum += sterm[k];
        double sum_usq = (double)(sparts[0] + sparts[1] + sparts[2] + sparts[3]);
        double s2sum   = (double)(sparts[4] + sparts[5] + sparts[6] + sparts[7]);
        double sum_dist = (double)NTRAIN * sum_usq
                        + (double)BATCH  * g_SUsq
                        - 2.0 * dotsum;
        double loss1 = (0.5 * sum_dist + g_corr)
                     / ((double)BATCH * (double)NTRAIN);
        double loss2 = 0.1 * s2sum / ((double)BATCH * (double)BITD);
        out[0] = (float)(loss1 + loss2);
    }
}

// ------------------------------------------------------------ launcher
extern "C" void kernel_launch(void* const* d_in, const int* in_sizes, int n_in,
                              void* d_out, int out_size) {
    const float* u   = (const float*)d_in[0];   // [512, 64]
    const float* y   = (const float*)d_in[1];   // [512, 100]
    const int*   ind = (const int*)  d_in[2];   // [512]
    const float* U   = (const float*)d_in[3];   // [100000, 64]
    const float* Y   = (const float*)d_in[4];   // [100000, 100]
    float* out = (float*)d_out;

    k_batch<<<BATCH_BLOCKS, 256>>>(u, y);
    k_mega<<<MEGA_BLOCKS, 256>>>(u, ind, U, Y, out);
}